// round 14
// baseline (speedup 1.0000x reference)
#include <cuda_runtime.h>
#include <cuda_fp16.h>
#include <cuda_bf16.h>
#include <cstdint>

// ======================= static scratch =======================
__device__ float  g_act[8388608];        // 2 ping-pong [8192,512] fp32 residual
__device__ __half g_qh[4194304];
__device__ __half g_kh[4194304];
__device__ __half g_vh[4194304];
__device__ __half g_cath[8388608];       // [8192,1024]: [:,:512]=x_q, [:,512:]=msg
__device__ __half g_zh[8388608];         // fp16 MLP hidden
__device__ __half g_mfinh[4194304];
__device__ float  g_coup[4202500];
__device__ __nv_bfloat16 g_Pb [4231200];
__device__ __nv_bfloat16 g_PTb[4231200];
__device__ float g_M [4100];
__device__ float g_w [4100];
__device__ float g_ev[4100];
__device__ float g_u [4100];
__device__ float g_vv[4100];
__device__ unsigned g_ctr4[4];
__device__ float g_chg[4][3];
__device__ float g_sn[8192];             // instnorm col sums  [8][1024]
__device__ float g_sq[8192];             // instnorm col sumsq [8][1024]
__device__ __half g_wpackh[9437184];
__device__ float  g_bpack[18432];
__device__ float  g_wmt[3145728];
__device__ __half g_W1h[12582912];
__device__ float  g_b1f[12288];
__device__ __half g_W2h[6291456];
__device__ __half g_Wfh[262144];

#define NORM_C  (-7.6246189861593985f)
#define LDS 36
#define GEMM_SMEM (4*128*LDS*4)
#define HLDS 72
#define GEMMH_SMEM (2*2*128*HLDS*2)
#define QP 72
#define FLASH_SMEM ((128 + 256)*QP*2)
#define PROWS 1032
#define PBATCH 1057800
#define SINK_TOL 8e-6f
#define SCL 0.18033688f                    // 0.125 * log2(e)

// ======================= primitives =======================
__device__ __forceinline__ unsigned f2tf(float x) {
    unsigned u; asm("cvt.rna.tf32.f32 %0, %1;" : "=r"(u) : "f"(x)); return u;
}
__device__ __forceinline__ float tfq(float x) { return __uint_as_float(f2tf(x)); }
__device__ __forceinline__ unsigned ex2h2(float lo, float hi) {
    __half2 h = __floats2half2_rn(lo, hi);
    unsigned u = *reinterpret_cast<unsigned*>(&h), r;
    asm("ex2.approx.f16x2 %0, %1;" : "=r"(r) : "r"(u));
    return r;
}
__device__ __forceinline__ void mma8(float* d, const unsigned* a, const unsigned* b) {
    asm volatile(
        "mma.sync.aligned.m16n8k8.row.col.f32.tf32.tf32.f32 "
        "{%0,%1,%2,%3}, {%4,%5,%6,%7}, {%8,%9}, {%0,%1,%2,%3};\n"
        : "+f"(d[0]), "+f"(d[1]), "+f"(d[2]), "+f"(d[3])
        : "r"(a[0]), "r"(a[1]), "r"(a[2]), "r"(a[3]), "r"(b[0]), "r"(b[1]));
}
__device__ __forceinline__ void mma16(float* d, const unsigned* a, unsigned b0, unsigned b1) {
    asm volatile(
        "mma.sync.aligned.m16n8k16.row.col.f32.f16.f16.f32 "
        "{%0,%1,%2,%3}, {%4,%5,%6,%7}, {%8,%9}, {%0,%1,%2,%3};\n"
        : "+f"(d[0]), "+f"(d[1]), "+f"(d[2]), "+f"(d[3])
        : "r"(a[0]), "r"(a[1]), "r"(a[2]), "r"(a[3]), "r"(b0), "r"(b1));
}
__device__ __forceinline__ void cpa16(void* s, const void* g) {
    unsigned sa = (unsigned)__cvta_generic_to_shared(s);
    asm volatile("cp.async.ca.shared.global [%0], [%1], 16;\n" :: "r"(sa), "l"(g));
}
#define LDSM4(d0,d1,d2,d3,addr) \
    asm volatile("ldmatrix.sync.aligned.m8n8.x4.shared.b16 {%0,%1,%2,%3}, [%4];\n" \
        : "=r"(d0), "=r"(d1), "=r"(d2), "=r"(d3) : "r"(addr))
#define LDSM2T(d0,d1,addr) \
    asm volatile("ldmatrix.sync.aligned.m8n8.x2.trans.shared.b16 {%0,%1}, [%2];\n" \
        : "=r"(d0), "=r"(d1) : "r"(addr))

// ======================= fp16 NT GEMM: 128x128, Kc=64, m16n8k16 ======================
// STATS: accumulate per-column sum/sumsq (post-bias fp32) into g_sn/g_sq.
template <int QKV, int STATS>
__global__ __launch_bounds__(256, 2) void gemm_h(
    const __half* __restrict__ A, int lda, long aS1,
    const __half* __restrict__ B, int ldb, long bS1,
    const float* __restrict__ bias,
    float* __restrict__ C, int ldc, long cS1,
    const float* __restrict__ resid,
    __half* __restrict__ Ch, int ldch,
    int K, float alpha)
{
    extern __shared__ __half hs[];
    const int z = blockIdx.z;
    A += z * aS1;  B += z * bS1;
    if (C) C += z * cS1;
    const int tid = threadIdx.x;
    const int bm = blockIdx.y * 128, bn = blockIdx.x * 128;
    const int KT = K >> 6;

    auto issue = [&](int kt, int st) {
        __half* as = hs + st * 18432;
        const __half* Ag = A + (long)bm * lda + kt * 64;
        #pragma unroll
        for (int i = 0; i < 4; i++) {
            int idx = tid + i * 256, r = idx >> 3, c8 = (idx & 7) * 8;
            cpa16(as + r * HLDS + c8, Ag + (long)r * lda + c8);
        }
        __half* bs = as + 9216;
        const __half* Bg = B + (long)bn * ldb + kt * 64;
        #pragma unroll
        for (int i = 0; i < 4; i++) {
            int idx = tid + i * 256, r = idx >> 3, c8 = (idx & 7) * 8;
            cpa16(bs + r * HLDS + c8, Bg + (long)r * ldb + c8);
        }
        asm volatile("cp.async.commit_group;\n");
    };

    float acc[4][4][4] = {};
    const int wid = tid >> 5, lane = tid & 31;
    const int wm = wid & 1, wn = wid >> 1, g = lane >> 2, q = lane & 3;
    const int l16 = lane & 15, hsel = (lane >> 4) * 8;
    const unsigned su = (unsigned)__cvta_generic_to_shared(hs);
    unsigned a_off[4], b_off[2];
    #pragma unroll
    for (int mt = 0; mt < 4; mt++)
        a_off[mt] = su + 2 * ((wm * 64 + mt * 16 + l16) * HLDS + hsel);
    #pragma unroll
    for (int p = 0; p < 2; p++)
        b_off[p] = su + 2 * (9216 + (wn * 32 + p * 16 + l16) * HLDS + hsel);

    issue(0, 0);
    for (int kt = 0; kt < KT; kt++) {
        int st = kt & 1;
        if (kt + 1 < KT) { issue(kt + 1, st ^ 1); asm volatile("cp.async.wait_group 1;\n"); }
        else             { asm volatile("cp.async.wait_group 0;\n"); }
        __syncthreads();
        const unsigned sb = st * (18432 * 2);
        #pragma unroll
        for (int j = 0; j < 4; j++) {
            unsigned af[4][4], bf[2][4];
            #pragma unroll
            for (int mt = 0; mt < 4; mt++)
                LDSM4(af[mt][0], af[mt][1], af[mt][2], af[mt][3],
                      a_off[mt] + sb + j * 32);
            #pragma unroll
            for (int p = 0; p < 2; p++)
                LDSM4(bf[p][0], bf[p][1], bf[p][2], bf[p][3],
                      b_off[p] + sb + j * 32);
            #pragma unroll
            for (int mt = 0; mt < 4; mt++)
                #pragma unroll
                for (int p = 0; p < 2; p++) {
                    mma16(acc[mt][2*p],   af[mt], bf[p][0], bf[p][2]);
                    mma16(acc[mt][2*p+1], af[mt], bf[p][1], bf[p][3]);
                }
        }
        __syncthreads();
    }

    const bool ldc_even = ((ldc & 1) == 0);
    float csum[4][2], csq[4][2];
    if (STATS) {
        #pragma unroll
        for (int nt = 0; nt < 4; nt++)
            #pragma unroll
            for (int j2 = 0; j2 < 2; j2++) { csum[nt][j2] = 0.f; csq[nt][j2] = 0.f; }
    }
    #pragma unroll
    for (int mt = 0; mt < 4; mt++)
        #pragma unroll
        for (int nt = 0; nt < 4; nt++) {
            int r0 = bm + wm * 64 + mt * 16 + g;
            int c0 = bn + wn * 32 + nt * 8 + q * 2;
            #pragma unroll
            for (int i2 = 0; i2 < 2; i2++) {
                long r = r0 + i2 * 8;
                float v0 = alpha * acc[mt][nt][i2 * 2 + 0];
                float v1 = alpha * acc[mt][nt][i2 * 2 + 1];
                if (bias) { v0 += bias[c0]; v1 += bias[c0 + 1]; }
                if (STATS) {
                    csum[nt][0] += v0; csq[nt][0] = fmaf(v0, v0, csq[nt][0]);
                    csum[nt][1] += v1; csq[nt][1] = fmaf(v1, v1, csq[nt][1]);
                }
                if (QKV) {
                    int rgn = c0 >> 9;
                    __half* O = (rgn == 0) ? g_qh : (rgn == 1) ? g_kh : g_vh;
                    *(__half2*)(O + r * 512 + (c0 & 511)) = __floats2half2_rn(v0, v1);
                } else {
                    if (resid) {
                        float2 rr = *(const float2*)(resid + r * ldc + c0);
                        v0 += rr.x; v1 += rr.y;
                    }
                    if (C) {
                        if (ldc_even) {
                            float2 w2; w2.x = v0; w2.y = v1;
                            *(float2*)(C + r * ldc + c0) = w2;
                        } else {
                            C[r * ldc + c0] = v0;
                            C[r * ldc + c0 + 1] = v1;
                        }
                    }
                    if (Ch) *(__half2*)(Ch + r * ldch + c0) = __floats2half2_rn(v0, v1);
                }
            }
        }
    if (STATS) {
        const int slice = bm >> 10;
        #pragma unroll
        for (int nt = 0; nt < 4; nt++)
            #pragma unroll
            for (int j2 = 0; j2 < 2; j2++) {
                int c = bn + wn * 32 + nt * 8 + q * 2 + j2;
                atomicAdd(&g_sn[slice * 1024 + c], csum[nt][j2]);
                atomicAdd(&g_sq[slice * 1024 + c], csq[nt][j2]);
            }
    }
}

// ======================= tf32 setup gemm: writes fp16 directly =======================
__global__ __launch_bounds__(256, 2) void gemm_tc(
    const float* __restrict__ A, int lda, long aS1,
    const float* __restrict__ B, int ldb, long bS1,
    __half* __restrict__ Ch, int ldc, long cS1, int K)
{
    extern __shared__ float smem[];
    const int z = blockIdx.z;
    A += z * aS1;  B += z * bS1;  Ch += z * cS1;
    const int tid = threadIdx.x;
    const int bm = blockIdx.y * 128, bn = blockIdx.x * 128;
    const int KT = K >> 5;

    auto issue = [&](int kt, int st) {
        const float* Ag = A + (long)bm * lda + kt * 32;
        float* as = smem + st * 128 * LDS;
        #pragma unroll
        for (int i = 0; i < 4; i++) {
            int idx = tid + i * 256, r = idx >> 3, c = (idx & 7) * 4;
            cpa16(as + r * LDS + c, Ag + (long)r * lda + c);
        }
        const float* Bg = B + (long)bn * ldb + kt * 32;
        float* bs = smem + 2 * 128 * LDS + st * 128 * LDS;
        #pragma unroll
        for (int i = 0; i < 4; i++) {
            int idx = tid + i * 256, r = idx >> 3, c = (idx & 7) * 4;
            cpa16(bs + r * LDS + c, Bg + (long)r * ldb + c);
        }
        asm volatile("cp.async.commit_group;\n");
    };

    float acc[4][4][4] = {};
    const int wid = tid >> 5, lane = tid & 31;
    const int wm = wid & 1, wn = wid >> 1, g = lane >> 2, q = lane & 3;
    const int t4 = lane >> 3, tr8 = lane & 7;
    const unsigned su = (unsigned)__cvta_generic_to_shared(smem);
    unsigned a_off[4], b_off[2];
    #pragma unroll
    for (int mt = 0; mt < 4; mt++)
        a_off[mt] = su + (((wm * 64 + mt * 16 + ((t4 & 1) << 3) + tr8) * LDS
                          + ((t4 >> 1) << 2)) << 2);
    #pragma unroll
    for (int p = 0; p < 2; p++)
        b_off[p] = su + ((2 * 128 * LDS + (wn * 32 + p * 16 + ((t4 >> 1) << 3) + tr8) * LDS
                          + ((t4 & 1) << 2)) << 2);

    issue(0, 0);
    for (int kt = 0; kt < KT; kt++) {
        int st = kt & 1;
        if (kt + 1 < KT) { issue(kt + 1, st ^ 1); asm volatile("cp.async.wait_group 1;\n"); }
        else             { asm volatile("cp.async.wait_group 0;\n"); }
        __syncthreads();
        const unsigned sb = st * (128 * LDS * 4);
        #pragma unroll
        for (int k8 = 0; k8 < 4; k8++) {
            unsigned af[4][4], bf[4][2];
            #pragma unroll
            for (int mt = 0; mt < 4; mt++) {
                LDSM4(af[mt][0], af[mt][1], af[mt][2], af[mt][3], a_off[mt] + sb + k8 * 32);
                #pragma unroll
                for (int e = 0; e < 4; e++) af[mt][e] = f2tf(__uint_as_float(af[mt][e]));
            }
            #pragma unroll
            for (int p = 0; p < 2; p++)
                LDSM4(bf[2*p][0], bf[2*p][1], bf[2*p+1][0], bf[2*p+1][1],
                      b_off[p] + sb + k8 * 32);
            #pragma unroll
            for (int mt = 0; mt < 4; mt++)
                #pragma unroll
                for (int nt = 0; nt < 4; nt++) mma8(acc[mt][nt], af[mt], bf[nt]);
        }
        __syncthreads();
    }
    #pragma unroll
    for (int mt = 0; mt < 4; mt++)
        #pragma unroll
        for (int nt = 0; nt < 4; nt++) {
            int r0 = bm + wm * 64 + mt * 16 + g;
            int c0 = bn + wn * 32 + nt * 8 + q * 2;
            #pragma unroll
            for (int i2 = 0; i2 < 2; i2++)
                *(__half2*)(Ch + (long)(r0 + i2 * 8) * ldc + c0) =
                    __floats2half2_rn(acc[mt][nt][i2 * 2], acc[mt][nt][i2 * 2 + 1]);
        }
}

// ======================= fp16 flash attention (f16x2 exp softmax) ====================
__global__ __launch_bounds__(256, 2) void flash_attn(int cross)
{
    extern __shared__ __half hs[];
    __half* Qs = hs;
    const int ts = blockIdx.z;
    const int os = cross ? (1 - ts) : ts;
    const int bh = blockIdx.y, b = bh >> 3, h = bh & 7;
    const int m0 = blockIdx.x * 128;
    const int tid = threadIdx.x, wid = tid >> 5, lane = tid & 31;
    const int g = lane >> 2, q = lane & 3;
    const int l16 = lane & 15, hsel = (lane >> 4) * 8;

    const __half* Qg = g_qh + (long)ts * 2097152 + (long)(b * 1024 + m0) * 512 + h * 64;
    const __half* Kg = g_kh + (long)os * 2097152 + (long)(b * 1024) * 512 + h * 64;
    const __half* Vg = g_vh + (long)os * 2097152 + (long)(b * 1024) * 512 + h * 64;

    #pragma unroll
    for (int i = 0; i < 4; i++) {
        int idx = tid + i * 256, r = idx >> 3, c = (idx & 7) * 8;
        cpa16(Qs + r * QP + c, Qg + (long)r * 512 + c);
    }
    asm volatile("cp.async.commit_group;\n");

    auto loadKV = [&](int t, int s) {
        __half* Kd = hs + (128 + 128 * s) * QP;
        __half* Vd = Kd + 64 * QP;
        #pragma unroll
        for (int i = 0; i < 2; i++) {
            int idx = tid + i * 256, r = idx >> 3, c = (idx & 7) * 8;
            cpa16(Kd + r * QP + c, Kg + (long)(t * 64 + r) * 512 + c);
        }
        #pragma unroll
        for (int i = 0; i < 2; i++) {
            int idx = tid + i * 256, r = idx >> 3, c = (idx & 7) * 8;
            cpa16(Vd + r * QP + c, Vg + (long)(t * 64 + r) * 512 + c);
        }
        asm volatile("cp.async.commit_group;\n");
    };
    loadKV(0, 0);
    loadKV(1, 1);

    const int wr = wid * 16;
    const unsigned su = (unsigned)__cvta_generic_to_shared(hs);
    const unsigned aq_off = su + 2 * ((wr + l16) * QP + hsel);
    unsigned bk_off0[4];
    #pragma unroll
    for (int p = 0; p < 4; p++)
        bk_off0[p] = su + 2 * ((128 + p * 16 + l16) * QP + hsel);
    const unsigned v_base0 = su + 2 * ((128 + 64 + l16) * QP);
    const unsigned stage_step = 128 * QP * 2;

    float mp0 = -1e30f, mp1 = -1e30f, l0 = 0.f, l1 = 0.f;
    float o[8][4] = {};

    for (int t = 0; t < 16; t++) {
        const int s = t & 1;
        const unsigned so = s * stage_step;
        if (t < 15) asm volatile("cp.async.wait_group 1;\n");
        else        asm volatile("cp.async.wait_group 0;\n");
        __syncthreads();
        float sc[8][4] = {};
        #pragma unroll
        for (int j = 0; j < 4; j++) {
            unsigned aq[4];
            LDSM4(aq[0], aq[1], aq[2], aq[3], aq_off + j * 32);
            #pragma unroll
            for (int p = 0; p < 4; p++) {
                unsigned bk[4];
                LDSM4(bk[0], bk[1], bk[2], bk[3], bk_off0[p] + so + j * 32);
                mma16(sc[2*p],   aq, bk[0], bk[2]);
                mma16(sc[2*p+1], aq, bk[1], bk[3]);
            }
        }
        float lm0 = -1e30f, lm1 = -1e30f;
        #pragma unroll
        for (int nt = 0; nt < 8; nt++) {
            #pragma unroll
            for (int e = 0; e < 4; e++) sc[nt][e] *= SCL;
            lm0 = fmaxf(lm0, fmaxf(sc[nt][0], sc[nt][1]));
            lm1 = fmaxf(lm1, fmaxf(sc[nt][2], sc[nt][3]));
        }
        lm0 = fmaxf(lm0, __shfl_xor_sync(0xffffffff, lm0, 1));
        lm0 = fmaxf(lm0, __shfl_xor_sync(0xffffffff, lm0, 2));
        lm1 = fmaxf(lm1, __shfl_xor_sync(0xffffffff, lm1, 1));
        lm1 = fmaxf(lm1, __shfl_xor_sync(0xffffffff, lm1, 2));
        float mn0 = fmaxf(mp0, lm0), mn1 = fmaxf(mp1, lm1);
        float a0 = exp2f(mp0 - mn0), a1 = exp2f(mp1 - mn1);
        unsigned ph[8][2];
        float ps0 = 0.f, ps1 = 0.f;
        #pragma unroll
        for (int nt = 0; nt < 8; nt++) {
            ph[nt][0] = ex2h2(sc[nt][0] - mn0, sc[nt][1] - mn0);
            ph[nt][1] = ex2h2(sc[nt][2] - mn1, sc[nt][3] - mn1);
            float2 f0 = __half22float2(*reinterpret_cast<__half2*>(&ph[nt][0]));
            float2 f1 = __half22float2(*reinterpret_cast<__half2*>(&ph[nt][1]));
            ps0 += f0.x + f0.y;
            ps1 += f1.x + f1.y;
        }
        ps0 += __shfl_xor_sync(0xffffffff, ps0, 1);
        ps0 += __shfl_xor_sync(0xffffffff, ps0, 2);
        ps1 += __shfl_xor_sync(0xffffffff, ps1, 1);
        ps1 += __shfl_xor_sync(0xffffffff, ps1, 2);
        l0 = l0 * a0 + ps0;  l1 = l1 * a1 + ps1;
        mp0 = mn0;  mp1 = mn1;
        #pragma unroll
        for (int tt = 0; tt < 8; tt++) {
            o[tt][0] *= a0; o[tt][1] *= a0; o[tt][2] *= a1; o[tt][3] *= a1;
        }
        #pragma unroll
        for (int j = 0; j < 4; j++) {
            unsigned ap[4];
            ap[0] = ph[2*j][0];
            ap[1] = ph[2*j][1];
            ap[2] = ph[2*j+1][0];
            ap[3] = ph[2*j+1][1];
            const unsigned vb = v_base0 + so + j * (16 * QP * 2);
            #pragma unroll
            for (int tt = 0; tt < 8; tt++) {
                unsigned bv0, bv1;
                LDSM2T(bv0, bv1, vb + tt * 16);
                mma16(o[tt], ap, bv0, bv1);
            }
        }
        __syncthreads();
        if (t + 2 < 16) loadKV(t + 2, s);
    }

    float inv0 = 1.f / l0, inv1 = 1.f / l1;
    __half* Og = g_cath + (long)(ts * 4096 + b * 1024 + m0 + wr) * 1024 + 512 + h * 64;
    #pragma unroll
    for (int tt = 0; tt < 8; tt++) {
        int c = tt * 8 + q * 2;
        *(__half2*)(Og + (long)g * 1024 + c) =
            __floats2half2_rn(o[tt][0] * inv0, o[tt][1] * inv0);
        *(__half2*)(Og + (long)(g + 8) * 1024 + c) =
            __floats2half2_rn(o[tt][2] * inv1, o[tt][3] * inv1);
    }
}

// ======================= pack / fold / norm / init ===================================
__global__ void pack_w(const float* __restrict__ Wq, const float* __restrict__ Wk,
                       const float* __restrict__ Wv, const float* __restrict__ bq,
                       const float* __restrict__ bk, const float* __restrict__ bv,
                       const float* __restrict__ Wm, const float* __restrict__ W1,
                       const float* __restrict__ W2, const float* __restrict__ Wf)
{
    long t = (long)blockIdx.x * 256 + threadIdx.x;
    if (t < 2359296) {
        long i = t / 196608; long rem = t - i * 196608;
        int row = (int)(rem >> 7), c4 = (int)(rem & 127) * 4;
        const float* src = row < 512 ? Wq : (row < 1024 ? Wk : Wv);
        float4 v = *(const float4*)(src + i * 262144 + (long)(row & 511) * 512 + c4);
        __half* d = g_wpackh + i * 786432 + (long)row * 512 + c4;
        *(__half2*)(d)     = __floats2half2_rn(v.x, v.y);
        *(__half2*)(d + 2) = __floats2half2_rn(v.z, v.w);
    }
    if (t < 1572864) {
        long i = t / 131072; long rem = t - i * 131072;
        int r = (int)(rem >> 7), c4 = (int)(rem & 127) * 4;
        float4 v = *(const float4*)(W1 + i * 1048576 + (long)r * 1024 + c4);
        __half* d = g_W1h + i * 1048576 + (long)r * 1024 + c4;
        *(__half2*)(d)     = __floats2half2_rn(v.x, v.y);
        *(__half2*)(d + 2) = __floats2half2_rn(v.z, v.w);
    }
    if (t < 1572864) {
        float4 v = *(const float4*)(W2 + t * 4);
        __half* d = g_W2h + t * 4;
        *(__half2*)(d)     = __floats2half2_rn(v.x, v.y);
        *(__half2*)(d + 2) = __floats2half2_rn(v.z, v.w);
    }
    if (t < 65536) {
        float4 v = *(const float4*)(Wf + t * 4);
        __half* d = g_Wfh + t * 4;
        *(__half2*)(d)     = __floats2half2_rn(v.x, v.y);
        *(__half2*)(d + 2) = __floats2half2_rn(v.z, v.w);
    }
    if (t < 18432) {
        long i = t / 1536; int row = (int)(t - i * 1536);
        const float* sb = row < 512 ? bq : (row < 1024 ? bk : bv);
        g_bpack[t] = sb[i * 512 + (row & 511)];
    }
    if (t < 8192) { g_sn[t] = 0.f; g_sq[t] = 0.f; }
    if (t < 3145728) {
        long i = t >> 18; long rem = t & 262143;
        int c = (int)(rem >> 9), o = (int)(rem & 511);
        int s = (c & 63) * 8 + (c >> 6);
        g_wmt[t] = tfq(Wm[i * 262144 + (long)o * 512 + s]);
    }
}

__global__ void fold_b1(const float* __restrict__ W1, const float* __restrict__ b1,
                        const float* __restrict__ bm)
{
    int gw = (blockIdx.x * 256 + threadIdx.x) >> 5;
    int lane = threadIdx.x & 31;
    if (gw >= 12288) return;
    int i = gw >> 10, r = gw & 1023;
    const float* row = W1 + (long)i * 1048576 + (long)r * 1024 + 512;
    const float* bv = bm + i * 512;
    float s = 0.f;
    for (int o = lane; o < 512; o += 32) s += row[o] * bv[o];
    #pragma unroll
    for (int o = 16; o; o >>= 1) s += __shfl_xor_sync(0xffffffff, s, o);
    if (lane == 0) g_b1f[gw] = b1[i * 1024 + r] + s;
}

// single-pass norm apply: stats precomputed by MLP1 epilogue; zero stats for next layer
__global__ __launch_bounds__(256) void instnorm_apply()
{
    int bb = blockIdx.x >> 4;
    int chunk = blockIdx.x & 15;
    int lane = threadIdx.x & 31, w = threadIdx.x >> 5;
    int c = chunk * 64 + lane * 2;
    float s0 = g_sn[bb * 1024 + c],     s1 = g_sn[bb * 1024 + c + 1];
    float q0 = g_sq[bb * 1024 + c],     q1 = g_sq[bb * 1024 + c + 1];
    float mx = s0 * (1.f / 1024.f),     my = s1 * (1.f / 1024.f);
    float ix = rsqrtf(q0 * (1.f / 1024.f) - mx * mx + 1e-5f);
    float iy = rsqrtf(q1 * (1.f / 1024.f) - my * my + 1e-5f);
    __syncthreads();
    if (w == 0) {
        g_sn[bb * 1024 + c] = 0.f; g_sn[bb * 1024 + c + 1] = 0.f;
        g_sq[bb * 1024 + c] = 0.f; g_sq[bb * 1024 + c + 1] = 0.f;
    }
    __half2* base = (__half2*)(g_zh + (long)bb * 1048576 + c);
    for (int n = w; n < 1024; n += 8) {
        float2 x = __half22float2(base[(long)n * 512]);
        base[(long)n * 512] = __floats2half2_rn(
            fmaxf((x.x - mx) * ix, 0.f), fmaxf((x.y - my) * iy, 0.f));
    }
}

// inputs -> fp32 residual stream + fp16 cat[:, :512]
__global__ void init_inputs(const float4* __restrict__ x0, const float4* __restrict__ x1)
{
    long t = (long)blockIdx.x * 256 + threadIdx.x;       // 1048576 float4
    float4 v = (t < 524288) ? x0[t] : x1[t - 524288];
    ((float4*)g_act)[t] = v;
    long r = t >> 7, c = (t & 127) * 4;
    __half* d = g_cath + r * 1024 + c;
    *(__half2*)(d)     = __floats2half2_rn(v.x, v.y);
    *(__half2*)(d + 2) = __floats2half2_rn(v.z, v.w);
}

// ======================= Sinkhorn ====================================================
// init folded in: bins, ev, counters handled here
__global__ __launch_bounds__(256) void sink_prep(const float* __restrict__ bin)
{
    const float a = *bin;
    int r = blockIdx.x;
    int b = r / 1025, i = r - b * 1025;
    float* row = g_coup + (long)b * 1050625 + (long)i * 1025;
    __nv_bfloat16* prow = g_Pb + (long)b * PBATCH + (long)i * PROWS;
    int t = threadIdx.x;
    if (r < 17) { int u = r * 256 + t; if (u < 4100) g_ev[u] = 1.f; }
    if (r == 0) {
        if (t < 4) g_ctr4[t] = 0;
        if (t >= 4 && t < 16) ((float*)g_chg)[t - 4] = 0.f;
    }
    if (i < 1024) { if (t == 0) row[1024] = a; }
    else          { for (int j = t; j < 1025; j += 256) row[j] = a; }
    __syncthreads();
    float m = -1e30f;
    for (int j = t; j < 1025; j += 256) m = fmaxf(m, row[j]);
    __shared__ float sm[256];
    sm[t] = m; __syncthreads();
    for (int o = 128; o > 0; o >>= 1) { if (t < o) sm[t] = fmaxf(sm[t], sm[t+o]); __syncthreads(); }
    m = sm[0];
    if (t == 0) g_M[r] = m;
    for (int j = t; j < PROWS; j += 256)
        prow[j] = (j < 1025) ? __float2bfloat16(__expf(row[j] - m))
                             : __float2bfloat16(0.f);
}

__global__ void transP()
{
    __shared__ __nv_bfloat16 tile[32][33];
    int b = blockIdx.z;
    int x0 = blockIdx.x * 32, y0 = blockIdx.y * 32;
    const __nv_bfloat16* src = g_Pb + (long)b * PBATCH;
    __nv_bfloat16* dst = g_PTb + (long)b * PBATCH;
    #pragma unroll
    for (int dy = 0; dy < 4; dy++) {
        int row = y0 + threadIdx.y + dy * 8, col = x0 + threadIdx.x;
        __nv_bfloat16 v = __float2bfloat16(0.f);
        if (row < 1025 && col < 1025) v = src[(long)row * PROWS + col];
        tile[threadIdx.y + dy * 8][threadIdx.x] = v;
    }
    __syncthreads();
    #pragma unroll
    for (int dy = 0; dy < 4; dy++) {
        int row = x0 + threadIdx.y + dy * 8, col = y0 + threadIdx.x;
        if (row < 1025 && col < PROWS)
            dst[(long)row * PROWS + col] = tile[threadIdx.x][threadIdx.y + dy * 8];
    }
}

__global__ __launch_bounds__(256) void sink_persist()
{
    const int tid = threadIdx.x, w = tid >> 5, lane = tid & 31;
    const int bb = blockIdx.x / 148, blk = blockIdx.x % 148;
    const int i = blk * 8 + w;
    const bool act = (i < 1025);
    __shared__ float vec[PROWS];
    const uint4* Pr4  = (const uint4*)(g_Pb  + (long)bb * PBATCH + (long)(act ? i : 0) * PROWS);
    const uint4* PTr4 = (const uint4*)(g_PTb + (long)bb * PBATCH + (long)(act ? i : 0) * PROWS);
    const float mu = (i < 1024) ? (1.f / 2048.f) : 0.5f;
    unsigned target = 0;
    volatile unsigned* ctr = &g_ctr4[bb];

    auto dot = [&](const uint4* R4) -> float {
        float s = 0.f;
        #pragma unroll 1
        for (int j4 = lane; j4 < 129; j4 += 32) {
            uint4 pk = R4[j4];
            const float* vp = vec + j4 * 8;
            float2 f0 = __bfloat1622float2(*reinterpret_cast<__nv_bfloat162*>(&pk.x));
            float2 f1 = __bfloat1622float2(*reinterpret_cast<__nv_bfloat162*>(&pk.y));
            float2 f2 = __bfloat1622float2(*reinterpret_cast<__nv_bfloat162*>(&pk.z));
            float2 f3 = __bfloat1622float2(*reinterpret_cast<__nv_bfloat162*>(&pk.w));
            s = fmaf(f0.x, vp[0], s); s = fmaf(f0.y, vp[1], s);
            s = fmaf(f1.x, vp[2], s); s = fmaf(f1.y, vp[3], s);
            s = fmaf(f2.x, vp[4], s); s = fmaf(f2.y, vp[5], s);
            s = fmaf(f3.x, vp[6], s); s = fmaf(f3.y, vp[7], s);
        }
        #pragma unroll
        for (int o = 16; o; o >>= 1) s += __shfl_xor_sync(0xffffffff, s, o);
        return s;
    };

    for (int it = 0; it < 100; it++) {
        const int slot = it % 3;
        for (int j = tid; j < PROWS; j += 256)
            vec[j] = (j < 1025) ? __ldcg(&g_ev[bb * 1025 + j]) : 0.f;
        __syncthreads();
        if (act) {
            float s = dot(Pr4);
            if (lane == 0) g_w[bb * 1025 + i] = mu / s;
        }
        __threadfence();
        __syncthreads();
        target += 148;
        if (tid == 0) {
            atomicAdd(&g_ctr4[bb], 1u);
            while (*ctr < target) __nanosleep(64);
        }
        __syncthreads();
        for (int j = tid; j < PROWS; j += 256)
            vec[j] = (j < 1025) ? __ldcg(&g_w[bb * 1025 + j]) : 0.f;
        __syncthreads();
        if (act) {
            float s = dot(PTr4);
            if (lane == 0) {
                float old = g_ev[bb * 1025 + i];
                float nv = mu / s;
                g_ev[bb * 1025 + i] = nv;
                float chg = fabsf(nv - old) / fmaxf(fabsf(old), 1e-30f);
                atomicMax((unsigned*)&g_chg[bb][slot], __float_as_uint(chg));
            }
        }
        if (blk == 0 && tid == 0)
            *(volatile float*)&g_chg[bb][(it + 1) % 3] = 0.f;
        __threadfence();
        __syncthreads();
        target += 148;
        if (tid == 0) {
            atomicAdd(&g_ctr4[bb], 1u);
            while (*ctr < target) __nanosleep(64);
        }
        __syncthreads();
        float chg = __ldcg((const float*)&g_chg[bb][slot]);
        if (it >= 12 && chg < SINK_TOL) break;
    }
}

__global__ void sink_uvfin()
{
    int t = blockIdx.x * 256 + threadIdx.x;
    if (t < 4100) {
        g_u[t]  = logf(g_w[t]) - g_M[t];
        g_vv[t] = logf(g_ev[t]);
    }
}

__global__ void final_out(float* __restrict__ out)
{
    long t = (long)blockIdx.x * 256 + threadIdx.x;
    if (t >= 4202500L) return;
    int b = (int)(t / 1050625);
    int rem = (int)(t - (long)b * 1050625);
    int i = rem / 1025, j = rem - i * 1025;
    out[t] = g_coup[t] + g_u[b * 1025 + i] + g_vv[b * 1025 + j] - NORM_C;
}

// ======================= driver ======================================================
extern "C" void kernel_launch(void* const* d_in, const int* in_sizes, int n_in,
                              void* d_out, int out_size)
{
    (void)in_sizes; (void)n_in; (void)out_size;
    const float* Wq = (const float*)d_in[2];  const float* bq = (const float*)d_in[3];
    const float* Wk = (const float*)d_in[4];  const float* bk = (const float*)d_in[5];
    const float* Wv = (const float*)d_in[6];  const float* bv = (const float*)d_in[7];
    const float* Wm = (const float*)d_in[8];  const float* bm = (const float*)d_in[9];
    const float* W1 = (const float*)d_in[10]; const float* b1 = (const float*)d_in[11];
    const float* W2 = (const float*)d_in[12]; const float* b2 = (const float*)d_in[13];
    const float* Wf = (const float*)d_in[14]; const float* bf = (const float*)d_in[15];
    const float* bin = (const float*)d_in[16];

    cudaFuncSetAttribute(gemm_tc,       cudaFuncAttributeMaxDynamicSharedMemorySize, GEMM_SMEM);
    cudaFuncSetAttribute(gemm_h<0,0>,   cudaFuncAttributeMaxDynamicSharedMemorySize, GEMMH_SMEM);
    cudaFuncSetAttribute(gemm_h<0,1>,   cudaFuncAttributeMaxDynamicSharedMemorySize, GEMMH_SMEM);
    cudaFuncSetAttribute(gemm_h<1,0>,   cudaFuncAttributeMaxDynamicSharedMemorySize, GEMMH_SMEM);
    cudaFuncSetAttribute(flash_attn,    cudaFuncAttributeMaxDynamicSharedMemorySize, FLASH_SMEM);

    float *pact, *pcoup, *pbpack, *pwmt, *pb1f;
    __half *pcath, *pzh, *pmfinh, *pwpackh, *pW1h, *pW2h, *pWfh;
    cudaGetSymbolAddress((void**)&pact,   g_act);
    cudaGetSymbolAddress((void**)&pcoup,  g_coup);
    cudaGetSymbolAddress((void**)&pbpack, g_bpack);
    cudaGetSymbolAddress((void**)&pwmt,   g_wmt);
    cudaGetSymbolAddress((void**)&pb1f,   g_b1f);
    cudaGetSymbolAddress((void**)&pcath,  g_cath);
    cudaGetSymbolAddress((void**)&pzh,    g_zh);
    cudaGetSymbolAddress((void**)&pmfinh, g_mfinh);
    cudaGetSymbolAddress((void**)&pwpackh,g_wpackh);
    cudaGetSymbolAddress((void**)&pW1h,   g_W1h);
    cudaGetSymbolAddress((void**)&pW2h,   g_W2h);
    cudaGetSymbolAddress((void**)&pWfh,   g_Wfh);

    pack_w<<<12288, 256>>>(Wq, Wk, Wv, bq, bk, bv, Wm, W1, W2, Wf);
    fold_b1<<<1536, 256>>>(W1, b1, bm);
    gemm_tc<<<dim3(4, 8, 12), 256, GEMM_SMEM>>>(
        W1 + 512, 1024, 1048576, pwmt, 512, 262144, pW1h + 512, 1024, 1048576, 512);

    float* cur = pact;
    float* nxt = pact + 4194304;
    init_inputs<<<4096, 256>>>((const float4*)d_in[0], (const float4*)d_in[1]);

    for (int i = 0; i < 12; i++) {
        const int cross = (i & 1);
        gemm_h<1,0><<<dim3(12, 64), 256, GEMMH_SMEM>>>(
            pcath, 1024, 0, pwpackh + (long)i * 786432, 512, 0,
            pbpack + i * 1536, nullptr, 0, 0, nullptr, nullptr, 0, 512, 1.f);
        flash_attn<<<dim3(8, 32, 2), 256, FLASH_SMEM>>>(cross);
        gemm_h<0,1><<<dim3(8, 64), 256, GEMMH_SMEM>>>(
            pcath, 1024, 0, pW1h + (long)i * 1048576, 1024, 0,
            pb1f + i * 1024, nullptr, 1024, 0, nullptr, pzh, 1024, 1024, 1.f);
        instnorm_apply<<<128, 256>>>();
        gemm_h<0,0><<<dim3(4, 64), 256, GEMMH_SMEM>>>(
            pzh, 1024, 0, pW2h + (long)i * 524288, 1024, 0,
            b2 + i * 512, nxt, 512, 0, cur, pcath, 1024, 1024, 1.f);
        float* tmp = cur; cur = nxt; nxt = tmp;
    }

    gemm_h<0,0><<<dim3(4, 64), 256, GEMMH_SMEM>>>(
        pcath, 1024, 0, pWfh, 512, 0, bf,
        nullptr, 0, 0, nullptr, pmfinh, 512, 512, 1.f);
    gemm_h<0,0><<<dim3(8, 8, 4), 256, GEMMH_SMEM>>>(
        pmfinh, 512, 524288, pmfinh + 2097152, 512, 524288, nullptr,
        pcoup, 1025, 1050625, nullptr, nullptr, 0, 512, 0.04419417382415922f);

    sink_prep<<<4100, 256>>>(bin);
    transP<<<dim3(33, 33, 4), dim3(32, 8)>>>();
    sink_persist<<<592, 256>>>();
    sink_uvfin<<<17, 256>>>();
    final_out<<<16417, 256>>>((float*)d_out);
}

// round 15
// speedup vs baseline: 1.0474x; 1.0474x over previous
#include <cuda_runtime.h>
#include <cuda_fp16.h>
#include <cuda_bf16.h>
#include <cstdint>

// ======================= static scratch =======================
__device__ float  g_act[8388608];        // 2 ping-pong [8192,512] fp32 residual
__device__ __half g_qh[4194304];
__device__ __half g_kh[4194304];
__device__ __half g_vh[4194304];
__device__ __half g_cath[8388608];       // [8192,1024]: [:,:512]=x_q, [:,512:]=msg
__device__ __half g_zh[8388608];         // fp16 MLP hidden (in-place instnorm)
__device__ __half g_mfinh[4194304];
__device__ float  g_coup[4202500];
__device__ __nv_bfloat16 g_Pb [4231200];
__device__ __nv_bfloat16 g_PTb[4231200];
__device__ float g_M [4100];
__device__ float g_w [4100];
__device__ float g_ev[4100];
__device__ float g_u [4100];
__device__ float g_vv[4100];
__device__ unsigned g_ctr4[4];
__device__ float g_chg[4][3];
__device__ __half g_wpackh[9437184];
__device__ float  g_bpack[18432];
__device__ float  g_wmt[3145728];
__device__ __half g_W1h[12582912];
__device__ float  g_b1f[12288];
__device__ __half g_W2h[6291456];
__device__ __half g_Wfh[262144];

#define NORM_C  (-7.6246189861593985f)
#define LDS 36
#define GEMM_SMEM (4*128*LDS*4)
#define HLDS 72
#define GEMMH_SMEM (2*2*128*HLDS*2)
#define QP 72
#define FLASH_SMEM ((128 + 256)*QP*2)
#define PROWS 1032
#define PBATCH 1057800
#define SINK_TOL 8e-6f
#define SCL 0.18033688f                    // 0.125 * log2(e)

// ======================= primitives =======================
__device__ __forceinline__ unsigned f2tf(float x) {
    unsigned u; asm("cvt.rna.tf32.f32 %0, %1;" : "=r"(u) : "f"(x)); return u;
}
__device__ __forceinline__ float tfq(float x) { return __uint_as_float(f2tf(x)); }
__device__ __forceinline__ unsigned ex2h2(float lo, float hi) {
    __half2 h = __floats2half2_rn(lo, hi);
    unsigned u = *reinterpret_cast<unsigned*>(&h), r;
    asm("ex2.approx.f16x2 %0, %1;" : "=r"(r) : "r"(u));
    return r;
}
__device__ __forceinline__ void mma8(float* d, const unsigned* a, const unsigned* b) {
    asm volatile(
        "mma.sync.aligned.m16n8k8.row.col.f32.tf32.tf32.f32 "
        "{%0,%1,%2,%3}, {%4,%5,%6,%7}, {%8,%9}, {%0,%1,%2,%3};\n"
        : "+f"(d[0]), "+f"(d[1]), "+f"(d[2]), "+f"(d[3])
        : "r"(a[0]), "r"(a[1]), "r"(a[2]), "r"(a[3]), "r"(b[0]), "r"(b[1]));
}
__device__ __forceinline__ void mma16(float* d, const unsigned* a, unsigned b0, unsigned b1) {
    asm volatile(
        "mma.sync.aligned.m16n8k16.row.col.f32.f16.f16.f32 "
        "{%0,%1,%2,%3}, {%4,%5,%6,%7}, {%8,%9}, {%0,%1,%2,%3};\n"
        : "+f"(d[0]), "+f"(d[1]), "+f"(d[2]), "+f"(d[3])
        : "r"(a[0]), "r"(a[1]), "r"(a[2]), "r"(a[3]), "r"(b0), "r"(b1));
}
__device__ __forceinline__ void cpa16(void* s, const void* g) {
    unsigned sa = (unsigned)__cvta_generic_to_shared(s);
    asm volatile("cp.async.ca.shared.global [%0], [%1], 16;\n" :: "r"(sa), "l"(g));
}
#define LDSM4(d0,d1,d2,d3,addr) \
    asm volatile("ldmatrix.sync.aligned.m8n8.x4.shared.b16 {%0,%1,%2,%3}, [%4];\n" \
        : "=r"(d0), "=r"(d1), "=r"(d2), "=r"(d3) : "r"(addr))
#define LDSM2T(d0,d1,addr) \
    asm volatile("ldmatrix.sync.aligned.m8n8.x2.trans.shared.b16 {%0,%1}, [%2];\n" \
        : "=r"(d0), "=r"(d1) : "r"(addr))

// ======================= fp16 NT GEMM: 128x128, Kc=64, m16n8k16 ======================
template <int QKV>
__global__ __launch_bounds__(256, 2) void gemm_h(
    const __half* __restrict__ A, int lda, long aS1,
    const __half* __restrict__ B, int ldb, long bS1,
    const float* __restrict__ bias,
    float* __restrict__ C, int ldc, long cS1,
    const float* __restrict__ resid,
    __half* __restrict__ Ch, int ldch,
    int K, float alpha)
{
    extern __shared__ __half hs[];
    const int z = blockIdx.z;
    A += z * aS1;  B += z * bS1;
    if (C) C += z * cS1;
    const int tid = threadIdx.x;
    const int bm = blockIdx.y * 128, bn = blockIdx.x * 128;
    const int KT = K >> 6;

    auto issue = [&](int kt, int st) {
        __half* as = hs + st * 18432;
        const __half* Ag = A + (long)bm * lda + kt * 64;
        #pragma unroll
        for (int i = 0; i < 4; i++) {
            int idx = tid + i * 256, r = idx >> 3, c8 = (idx & 7) * 8;
            cpa16(as + r * HLDS + c8, Ag + (long)r * lda + c8);
        }
        __half* bs = as + 9216;
        const __half* Bg = B + (long)bn * ldb + kt * 64;
        #pragma unroll
        for (int i = 0; i < 4; i++) {
            int idx = tid + i * 256, r = idx >> 3, c8 = (idx & 7) * 8;
            cpa16(bs + r * HLDS + c8, Bg + (long)r * ldb + c8);
        }
        asm volatile("cp.async.commit_group;\n");
    };

    float acc[4][4][4] = {};
    const int wid = tid >> 5, lane = tid & 31;
    const int wm = wid & 1, wn = wid >> 1, g = lane >> 2, q = lane & 3;
    const int l16 = lane & 15, hsel = (lane >> 4) * 8;
    const unsigned su = (unsigned)__cvta_generic_to_shared(hs);
    unsigned a_off[4], b_off[2];
    #pragma unroll
    for (int mt = 0; mt < 4; mt++)
        a_off[mt] = su + 2 * ((wm * 64 + mt * 16 + l16) * HLDS + hsel);
    #pragma unroll
    for (int p = 0; p < 2; p++)
        b_off[p] = su + 2 * (9216 + (wn * 32 + p * 16 + l16) * HLDS + hsel);

    issue(0, 0);
    for (int kt = 0; kt < KT; kt++) {
        int st = kt & 1;
        if (kt + 1 < KT) { issue(kt + 1, st ^ 1); asm volatile("cp.async.wait_group 1;\n"); }
        else             { asm volatile("cp.async.wait_group 0;\n"); }
        __syncthreads();
        const unsigned sb = st * (18432 * 2);
        #pragma unroll
        for (int j = 0; j < 4; j++) {
            unsigned af[4][4], bf[2][4];
            #pragma unroll
            for (int mt = 0; mt < 4; mt++)
                LDSM4(af[mt][0], af[mt][1], af[mt][2], af[mt][3],
                      a_off[mt] + sb + j * 32);
            #pragma unroll
            for (int p = 0; p < 2; p++)
                LDSM4(bf[p][0], bf[p][1], bf[p][2], bf[p][3],
                      b_off[p] + sb + j * 32);
            #pragma unroll
            for (int mt = 0; mt < 4; mt++)
                #pragma unroll
                for (int p = 0; p < 2; p++) {
                    mma16(acc[mt][2*p],   af[mt], bf[p][0], bf[p][2]);
                    mma16(acc[mt][2*p+1], af[mt], bf[p][1], bf[p][3]);
                }
        }
        __syncthreads();
    }

    const bool ldc_even = ((ldc & 1) == 0);
    #pragma unroll
    for (int mt = 0; mt < 4; mt++)
        #pragma unroll
        for (int nt = 0; nt < 4; nt++) {
            int r0 = bm + wm * 64 + mt * 16 + g;
            int c0 = bn + wn * 32 + nt * 8 + q * 2;
            #pragma unroll
            for (int i2 = 0; i2 < 2; i2++) {
                long r = r0 + i2 * 8;
                float v0 = alpha * acc[mt][nt][i2 * 2 + 0];
                float v1 = alpha * acc[mt][nt][i2 * 2 + 1];
                if (bias) { v0 += bias[c0]; v1 += bias[c0 + 1]; }
                if (QKV) {
                    int rgn = c0 >> 9;
                    __half* O = (rgn == 0) ? g_qh : (rgn == 1) ? g_kh : g_vh;
                    *(__half2*)(O + r * 512 + (c0 & 511)) = __floats2half2_rn(v0, v1);
                } else {
                    if (resid) {
                        float2 rr = *(const float2*)(resid + r * ldc + c0);
                        v0 += rr.x; v1 += rr.y;
                    }
                    if (C) {
                        if (ldc_even) {
                            float2 w2; w2.x = v0; w2.y = v1;
                            *(float2*)(C + r * ldc + c0) = w2;
                        } else {
                            C[r * ldc + c0] = v0;
                            C[r * ldc + c0 + 1] = v1;
                        }
                    }
                    if (Ch) *(__half2*)(Ch + r * ldch + c0) = __floats2half2_rn(v0, v1);
                }
            }
        }
}

// ======================= tf32 setup gemm: writes fp16 directly =======================
__global__ __launch_bounds__(256, 2) void gemm_tc(
    const float* __restrict__ A, int lda, long aS1,
    const float* __restrict__ B, int ldb, long bS1,
    __half* __restrict__ Ch, int ldc, long cS1, int K)
{
    extern __shared__ float smem[];
    const int z = blockIdx.z;
    A += z * aS1;  B += z * bS1;  Ch += z * cS1;
    const int tid = threadIdx.x;
    const int bm = blockIdx.y * 128, bn = blockIdx.x * 128;
    const int KT = K >> 5;

    auto issue = [&](int kt, int st) {
        const float* Ag = A + (long)bm * lda + kt * 32;
        float* as = smem + st * 128 * LDS;
        #pragma unroll
        for (int i = 0; i < 4; i++) {
            int idx = tid + i * 256, r = idx >> 3, c = (idx & 7) * 4;
            cpa16(as + r * LDS + c, Ag + (long)r * lda + c);
        }
        const float* Bg = B + (long)bn * ldb + kt * 32;
        float* bs = smem + 2 * 128 * LDS + st * 128 * LDS;
        #pragma unroll
        for (int i = 0; i < 4; i++) {
            int idx = tid + i * 256, r = idx >> 3, c = (idx & 7) * 4;
            cpa16(bs + r * LDS + c, Bg + (long)r * ldb + c);
        }
        asm volatile("cp.async.commit_group;\n");
    };

    float acc[4][4][4] = {};
    const int wid = tid >> 5, lane = tid & 31;
    const int wm = wid & 1, wn = wid >> 1, g = lane >> 2, q = lane & 3;
    const int t4 = lane >> 3, tr8 = lane & 7;
    const unsigned su = (unsigned)__cvta_generic_to_shared(smem);
    unsigned a_off[4], b_off[2];
    #pragma unroll
    for (int mt = 0; mt < 4; mt++)
        a_off[mt] = su + (((wm * 64 + mt * 16 + ((t4 & 1) << 3) + tr8) * LDS
                          + ((t4 >> 1) << 2)) << 2);
    #pragma unroll
    for (int p = 0; p < 2; p++)
        b_off[p] = su + ((2 * 128 * LDS + (wn * 32 + p * 16 + ((t4 >> 1) << 3) + tr8) * LDS
                          + ((t4 & 1) << 2)) << 2);

    issue(0, 0);
    for (int kt = 0; kt < KT; kt++) {
        int st = kt & 1;
        if (kt + 1 < KT) { issue(kt + 1, st ^ 1); asm volatile("cp.async.wait_group 1;\n"); }
        else             { asm volatile("cp.async.wait_group 0;\n"); }
        __syncthreads();
        const unsigned sb = st * (128 * LDS * 4);
        #pragma unroll
        for (int k8 = 0; k8 < 4; k8++) {
            unsigned af[4][4], bf[4][2];
            #pragma unroll
            for (int mt = 0; mt < 4; mt++) {
                LDSM4(af[mt][0], af[mt][1], af[mt][2], af[mt][3], a_off[mt] + sb + k8 * 32);
                #pragma unroll
                for (int e = 0; e < 4; e++) af[mt][e] = f2tf(__uint_as_float(af[mt][e]));
            }
            #pragma unroll
            for (int p = 0; p < 2; p++)
                LDSM4(bf[2*p][0], bf[2*p][1], bf[2*p+1][0], bf[2*p+1][1],
                      b_off[p] + sb + k8 * 32);
            #pragma unroll
            for (int mt = 0; mt < 4; mt++)
                #pragma unroll
                for (int nt = 0; nt < 4; nt++) mma8(acc[mt][nt], af[mt], bf[nt]);
        }
        __syncthreads();
    }
    #pragma unroll
    for (int mt = 0; mt < 4; mt++)
        #pragma unroll
        for (int nt = 0; nt < 4; nt++) {
            int r0 = bm + wm * 64 + mt * 16 + g;
            int c0 = bn + wn * 32 + nt * 8 + q * 2;
            #pragma unroll
            for (int i2 = 0; i2 < 2; i2++)
                *(__half2*)(Ch + (long)(r0 + i2 * 8) * ldc + c0) =
                    __floats2half2_rn(acc[mt][nt][i2 * 2], acc[mt][nt][i2 * 2 + 1]);
        }
}

// ======================= fp16 flash attention (f16x2 exp softmax) ====================
__global__ __launch_bounds__(256, 2) void flash_attn(int cross)
{
    extern __shared__ __half hs[];
    __half* Qs = hs;
    const int ts = blockIdx.z;
    const int os = cross ? (1 - ts) : ts;
    const int bh = blockIdx.y, b = bh >> 3, h = bh & 7;
    const int m0 = blockIdx.x * 128;
    const int tid = threadIdx.x, wid = tid >> 5, lane = tid & 31;
    const int g = lane >> 2, q = lane & 3;
    const int l16 = lane & 15, hsel = (lane >> 4) * 8;

    const __half* Qg = g_qh + (long)ts * 2097152 + (long)(b * 1024 + m0) * 512 + h * 64;
    const __half* Kg = g_kh + (long)os * 2097152 + (long)(b * 1024) * 512 + h * 64;
    const __half* Vg = g_vh + (long)os * 2097152 + (long)(b * 1024) * 512 + h * 64;

    #pragma unroll
    for (int i = 0; i < 4; i++) {
        int idx = tid + i * 256, r = idx >> 3, c = (idx & 7) * 8;
        cpa16(Qs + r * QP + c, Qg + (long)r * 512 + c);
    }
    asm volatile("cp.async.commit_group;\n");

    auto loadKV = [&](int t, int s) {
        __half* Kd = hs + (128 + 128 * s) * QP;
        __half* Vd = Kd + 64 * QP;
        #pragma unroll
        for (int i = 0; i < 2; i++) {
            int idx = tid + i * 256, r = idx >> 3, c = (idx & 7) * 8;
            cpa16(Kd + r * QP + c, Kg + (long)(t * 64 + r) * 512 + c);
        }
        #pragma unroll
        for (int i = 0; i < 2; i++) {
            int idx = tid + i * 256, r = idx >> 3, c = (idx & 7) * 8;
            cpa16(Vd + r * QP + c, Vg + (long)(t * 64 + r) * 512 + c);
        }
        asm volatile("cp.async.commit_group;\n");
    };
    loadKV(0, 0);
    loadKV(1, 1);

    const int wr = wid * 16;
    const unsigned su = (unsigned)__cvta_generic_to_shared(hs);
    const unsigned aq_off = su + 2 * ((wr + l16) * QP + hsel);
    unsigned bk_off0[4];
    #pragma unroll
    for (int p = 0; p < 4; p++)
        bk_off0[p] = su + 2 * ((128 + p * 16 + l16) * QP + hsel);
    const unsigned v_base0 = su + 2 * ((128 + 64 + l16) * QP);
    const unsigned stage_step = 128 * QP * 2;

    float mp0 = -1e30f, mp1 = -1e30f, l0 = 0.f, l1 = 0.f;
    float o[8][4] = {};

    for (int t = 0; t < 16; t++) {
        const int s = t & 1;
        const unsigned so = s * stage_step;
        if (t < 15) asm volatile("cp.async.wait_group 1;\n");
        else        asm volatile("cp.async.wait_group 0;\n");
        __syncthreads();
        float sc[8][4] = {};
        #pragma unroll
        for (int j = 0; j < 4; j++) {
            unsigned aq[4];
            LDSM4(aq[0], aq[1], aq[2], aq[3], aq_off + j * 32);
            #pragma unroll
            for (int p = 0; p < 4; p++) {
                unsigned bk[4];
                LDSM4(bk[0], bk[1], bk[2], bk[3], bk_off0[p] + so + j * 32);
                mma16(sc[2*p],   aq, bk[0], bk[2]);
                mma16(sc[2*p+1], aq, bk[1], bk[3]);
            }
        }
        float lm0 = -1e30f, lm1 = -1e30f;
        #pragma unroll
        for (int nt = 0; nt < 8; nt++) {
            #pragma unroll
            for (int e = 0; e < 4; e++) sc[nt][e] *= SCL;
            lm0 = fmaxf(lm0, fmaxf(sc[nt][0], sc[nt][1]));
            lm1 = fmaxf(lm1, fmaxf(sc[nt][2], sc[nt][3]));
        }
        lm0 = fmaxf(lm0, __shfl_xor_sync(0xffffffff, lm0, 1));
        lm0 = fmaxf(lm0, __shfl_xor_sync(0xffffffff, lm0, 2));
        lm1 = fmaxf(lm1, __shfl_xor_sync(0xffffffff, lm1, 1));
        lm1 = fmaxf(lm1, __shfl_xor_sync(0xffffffff, lm1, 2));
        float mn0 = fmaxf(mp0, lm0), mn1 = fmaxf(mp1, lm1);
        float a0 = exp2f(mp0 - mn0), a1 = exp2f(mp1 - mn1);
        unsigned ph[8][2];
        float ps0 = 0.f, ps1 = 0.f;
        #pragma unroll
        for (int nt = 0; nt < 8; nt++) {
            ph[nt][0] = ex2h2(sc[nt][0] - mn0, sc[nt][1] - mn0);
            ph[nt][1] = ex2h2(sc[nt][2] - mn1, sc[nt][3] - mn1);
            float2 f0 = __half22float2(*reinterpret_cast<__half2*>(&ph[nt][0]));
            float2 f1 = __half22float2(*reinterpret_cast<__half2*>(&ph[nt][1]));
            ps0 += f0.x + f0.y;
            ps1 += f1.x + f1.y;
        }
        ps0 += __shfl_xor_sync(0xffffffff, ps0, 1);
        ps0 += __shfl_xor_sync(0xffffffff, ps0, 2);
        ps1 += __shfl_xor_sync(0xffffffff, ps1, 1);
        ps1 += __shfl_xor_sync(0xffffffff, ps1, 2);
        l0 = l0 * a0 + ps0;  l1 = l1 * a1 + ps1;
        mp0 = mn0;  mp1 = mn1;
        #pragma unroll
        for (int tt = 0; tt < 8; tt++) {
            o[tt][0] *= a0; o[tt][1] *= a0; o[tt][2] *= a1; o[tt][3] *= a1;
        }
        #pragma unroll
        for (int j = 0; j < 4; j++) {
            unsigned ap[4];
            ap[0] = ph[2*j][0];
            ap[1] = ph[2*j][1];
            ap[2] = ph[2*j+1][0];
            ap[3] = ph[2*j+1][1];
            const unsigned vb = v_base0 + so + j * (16 * QP * 2);
            #pragma unroll
            for (int tt = 0; tt < 8; tt++) {
                unsigned bv0, bv1;
                LDSM2T(bv0, bv1, vb + tt * 16);
                mma16(o[tt], ap, bv0, bv1);
            }
        }
        __syncthreads();
        if (t + 2 < 16) loadKV(t + 2, s);
    }

    float inv0 = 1.f / l0, inv1 = 1.f / l1;
    __half* Og = g_cath + (long)(ts * 4096 + b * 1024 + m0 + wr) * 1024 + 512 + h * 64;
    #pragma unroll
    for (int tt = 0; tt < 8; tt++) {
        int c = tt * 8 + q * 2;
        *(__half2*)(Og + (long)g * 1024 + c) =
            __floats2half2_rn(o[tt][0] * inv0, o[tt][1] * inv0);
        *(__half2*)(Og + (long)(g + 8) * 1024 + c) =
            __floats2half2_rn(o[tt][2] * inv1, o[tt][3] * inv1);
    }
}

// ======================= pack / fold / norm / init ===================================
__global__ void pack_w(const float* __restrict__ Wq, const float* __restrict__ Wk,
                       const float* __restrict__ Wv, const float* __restrict__ bq,
                       const float* __restrict__ bk, const float* __restrict__ bv,
                       const float* __restrict__ Wm, const float* __restrict__ W1,
                       const float* __restrict__ W2, const float* __restrict__ Wf)
{
    long t = (long)blockIdx.x * 256 + threadIdx.x;
    if (t < 2359296) {
        long i = t / 196608; long rem = t - i * 196608;
        int row = (int)(rem >> 7), c4 = (int)(rem & 127) * 4;
        const float* src = row < 512 ? Wq : (row < 1024 ? Wk : Wv);
        float4 v = *(const float4*)(src + i * 262144 + (long)(row & 511) * 512 + c4);
        __half* d = g_wpackh + i * 786432 + (long)row * 512 + c4;
        *(__half2*)(d)     = __floats2half2_rn(v.x, v.y);
        *(__half2*)(d + 2) = __floats2half2_rn(v.z, v.w);
    }
    if (t < 1572864) {
        long i = t / 131072; long rem = t - i * 131072;
        int r = (int)(rem >> 7), c4 = (int)(rem & 127) * 4;
        float4 v = *(const float4*)(W1 + i * 1048576 + (long)r * 1024 + c4);
        __half* d = g_W1h + i * 1048576 + (long)r * 1024 + c4;
        *(__half2*)(d)     = __floats2half2_rn(v.x, v.y);
        *(__half2*)(d + 2) = __floats2half2_rn(v.z, v.w);
    }
    if (t < 1572864) {
        float4 v = *(const float4*)(W2 + t * 4);
        __half* d = g_W2h + t * 4;
        *(__half2*)(d)     = __floats2half2_rn(v.x, v.y);
        *(__half2*)(d + 2) = __floats2half2_rn(v.z, v.w);
    }
    if (t < 65536) {
        float4 v = *(const float4*)(Wf + t * 4);
        __half* d = g_Wfh + t * 4;
        *(__half2*)(d)     = __floats2half2_rn(v.x, v.y);
        *(__half2*)(d + 2) = __floats2half2_rn(v.z, v.w);
    }
    if (t < 18432) {
        long i = t / 1536; int row = (int)(t - i * 1536);
        const float* sb = row < 512 ? bq : (row < 1024 ? bk : bv);
        g_bpack[t] = sb[i * 512 + (row & 511)];
    }
    if (t < 3145728) {
        long i = t >> 18; long rem = t & 262143;
        int c = (int)(rem >> 9), o = (int)(rem & 511);
        int s = (c & 63) * 8 + (c >> 6);
        g_wmt[t] = tfq(Wm[i * 262144 + (long)o * 512 + s]);
    }
}

__global__ void fold_b1(const float* __restrict__ W1, const float* __restrict__ b1,
                        const float* __restrict__ bm)
{
    int gw = (blockIdx.x * 256 + threadIdx.x) >> 5;
    int lane = threadIdx.x & 31;
    if (gw >= 12288) return;
    int i = gw >> 10, r = gw & 1023;
    const float* row = W1 + (long)i * 1048576 + (long)r * 1024 + 512;
    const float* bv = bm + i * 512;
    float s = 0.f;
    for (int o = lane; o < 512; o += 32) s += row[o] * bv[o];
    #pragma unroll
    for (int o = 16; o; o >>= 1) s += __shfl_xor_sync(0xffffffff, s, o);
    if (lane == 0) g_b1f[gw] = b1[i * 1024 + r] + s;
}

// two-pass fp16 in-place instnorm (no atomics)
__global__ __launch_bounds__(256) void instnorm_relu()
{
    int bb = blockIdx.x >> 4;
    int chunk = blockIdx.x & 15;
    int lane = threadIdx.x & 31, w = threadIdx.x >> 5;
    int c = chunk * 64 + lane * 2;
    __half2* base = (__half2*)(g_zh + (long)bb * 1048576 + c);
    float sx = 0.f, sy = 0.f, qx = 0.f, qy = 0.f;
    for (int n = w; n < 1024; n += 8) {
        float2 x = __half22float2(base[(long)n * 512]);
        sx += x.x; sy += x.y;
        qx = fmaf(x.x, x.x, qx); qy = fmaf(x.y, x.y, qy);
    }
    __shared__ float shx[8][32], shy[8][32], sqx[8][32], sqy[8][32];
    shx[w][lane] = sx; shy[w][lane] = sy;
    sqx[w][lane] = qx; sqy[w][lane] = qy;
    __syncthreads();
    if (w == 0) {
        float ax = 0, ay = 0, bx = 0, by = 0;
        #pragma unroll
        for (int i = 0; i < 8; i++) {
            ax += shx[i][lane]; ay += shy[i][lane];
            bx += sqx[i][lane]; by += sqy[i][lane];
        }
        float mx = ax * (1.f/1024.f), my = ay * (1.f/1024.f);
        shx[0][lane] = mx;
        shy[0][lane] = my;
        sqx[0][lane] = rsqrtf(bx * (1.f/1024.f) - mx * mx + 1e-5f);
        sqy[0][lane] = rsqrtf(by * (1.f/1024.f) - my * my + 1e-5f);
    }
    __syncthreads();
    float mx = shx[0][lane], my = shy[0][lane];
    float ix = sqx[0][lane], iy = sqy[0][lane];
    for (int n = w; n < 1024; n += 8) {
        float2 x = __half22float2(base[(long)n * 512]);
        base[(long)n * 512] = __floats2half2_rn(
            fmaxf((x.x - mx) * ix, 0.f), fmaxf((x.y - my) * iy, 0.f));
    }
}

// inputs -> fp32 residual stream + fp16 cat[:, :512]
__global__ void init_inputs(const float4* __restrict__ x0, const float4* __restrict__ x1)
{
    long t = (long)blockIdx.x * 256 + threadIdx.x;       // 1048576 float4
    float4 v = (t < 524288) ? x0[t] : x1[t - 524288];
    ((float4*)g_act)[t] = v;
    long r = t >> 7, c = (t & 127) * 4;
    __half* d = g_cath + r * 1024 + c;
    *(__half2*)(d)     = __floats2half2_rn(v.x, v.y);
    *(__half2*)(d + 2) = __floats2half2_rn(v.z, v.w);
}

// ======================= Sinkhorn ====================================================
__global__ __launch_bounds__(256) void sink_prep(const float* __restrict__ bin)
{
    const float a = *bin;
    int r = blockIdx.x;
    int b = r / 1025, i = r - b * 1025;
    float* row = g_coup + (long)b * 1050625 + (long)i * 1025;
    __nv_bfloat16* prow = g_Pb + (long)b * PBATCH + (long)i * PROWS;
    int t = threadIdx.x;
    if (r < 17) { int u = r * 256 + t; if (u < 4100) g_ev[u] = 1.f; }
    if (r == 0) {
        if (t < 4) g_ctr4[t] = 0;
        if (t >= 4 && t < 16) ((float*)g_chg)[t - 4] = 0.f;
    }
    if (i < 1024) { if (t == 0) row[1024] = a; }
    else          { for (int j = t; j < 1025; j += 256) row[j] = a; }
    __syncthreads();
    float m = -1e30f;
    for (int j = t; j < 1025; j += 256) m = fmaxf(m, row[j]);
    __shared__ float sm[256];
    sm[t] = m; __syncthreads();
    for (int o = 128; o > 0; o >>= 1) { if (t < o) sm[t] = fmaxf(sm[t], sm[t+o]); __syncthreads(); }
    m = sm[0];
    if (t == 0) g_M[r] = m;
    for (int j = t; j < PROWS; j += 256)
        prow[j] = (j < 1025) ? __float2bfloat16(__expf(row[j] - m))
                             : __float2bfloat16(0.f);
}

__global__ void transP()
{
    __shared__ __nv_bfloat16 tile[32][33];
    int b = blockIdx.z;
    int x0 = blockIdx.x * 32, y0 = blockIdx.y * 32;
    const __nv_bfloat16* src = g_Pb + (long)b * PBATCH;
    __nv_bfloat16* dst = g_PTb + (long)b * PBATCH;
    #pragma unroll
    for (int dy = 0; dy < 4; dy++) {
        int row = y0 + threadIdx.y + dy * 8, col = x0 + threadIdx.x;
        __nv_bfloat16 v = __float2bfloat16(0.f);
        if (row < 1025 && col < 1025) v = src[(long)row * PROWS + col];
        tile[threadIdx.y + dy * 8][threadIdx.x] = v;
    }
    __syncthreads();
    #pragma unroll
    for (int dy = 0; dy < 4; dy++) {
        int row = x0 + threadIdx.y + dy * 8, col = y0 + threadIdx.x;
        if (row < 1025 && col < PROWS)
            dst[(long)row * PROWS + col] = tile[threadIdx.x][threadIdx.y + dy * 8];
    }
}

__global__ __launch_bounds__(256) void sink_persist()
{
    const int tid = threadIdx.x, w = tid >> 5, lane = tid & 31;
    const int bb = blockIdx.x / 148, blk = blockIdx.x % 148;
    const int i = blk * 8 + w;
    const bool act = (i < 1025);
    __shared__ float vec[PROWS];
    const uint4* Pr4  = (const uint4*)(g_Pb  + (long)bb * PBATCH + (long)(act ? i : 0) * PROWS);
    const uint4* PTr4 = (const uint4*)(g_PTb + (long)bb * PBATCH + (long)(act ? i : 0) * PROWS);
    const float mu = (i < 1024) ? (1.f / 2048.f) : 0.5f;
    unsigned target = 0;
    volatile unsigned* ctr = &g_ctr4[bb];

    auto dot = [&](const uint4* R4) -> float {
        float s = 0.f;
        #pragma unroll 1
        for (int j4 = lane; j4 < 129; j4 += 32) {
            uint4 pk = R4[j4];
            const float* vp = vec + j4 * 8;
            float2 f0 = __bfloat1622float2(*reinterpret_cast<__nv_bfloat162*>(&pk.x));
            float2 f1 = __bfloat1622float2(*reinterpret_cast<__nv_bfloat162*>(&pk.y));
            float2 f2 = __bfloat1622float2(*reinterpret_cast<__nv_bfloat162*>(&pk.z));
            float2 f3 = __bfloat1622float2(*reinterpret_cast<__nv_bfloat162*>(&pk.w));
            s = fmaf(f0.x, vp[0], s); s = fmaf(f0.y, vp[1], s);
            s = fmaf(f1.x, vp[2], s); s = fmaf(f1.y, vp[3], s);
            s = fmaf(f2.x, vp[4], s); s = fmaf(f2.y, vp[5], s);
            s = fmaf(f3.x, vp[6], s); s = fmaf(f3.y, vp[7], s);
        }
        #pragma unroll
        for (int o = 16; o; o >>= 1) s += __shfl_xor_sync(0xffffffff, s, o);
        return s;
    };

    for (int it = 0; it < 100; it++) {
        const int slot = it % 3;
        for (int j = tid; j < PROWS; j += 256)
            vec[j] = (j < 1025) ? __ldcg(&g_ev[bb * 1025 + j]) : 0.f;
        __syncthreads();
        if (act) {
            float s = dot(Pr4);
            if (lane == 0) g_w[bb * 1025 + i] = mu / s;
        }
        __threadfence();
        __syncthreads();
        target += 148;
        if (tid == 0) {
            atomicAdd(&g_ctr4[bb], 1u);
            while (*ctr < target) __nanosleep(64);
        }
        __syncthreads();
        for (int j = tid; j < PROWS; j += 256)
            vec[j] = (j < 1025) ? __ldcg(&g_w[bb * 1025 + j]) : 0.f;
        __syncthreads();
        if (act) {
            float s = dot(PTr4);
            if (lane == 0) {
                float old = g_ev[bb * 1025 + i];
                float nv = mu / s;
                g_ev[bb * 1025 + i] = nv;
                float chg = fabsf(nv - old) / fmaxf(fabsf(old), 1e-30f);
                atomicMax((unsigned*)&g_chg[bb][slot], __float_as_uint(chg));
            }
        }
        if (blk == 0 && tid == 0)
            *(volatile float*)&g_chg[bb][(it + 1) % 3] = 0.f;
        __threadfence();
        __syncthreads();
        target += 148;
        if (tid == 0) {
            atomicAdd(&g_ctr4[bb], 1u);
            while (*ctr < target) __nanosleep(64);
        }
        __syncthreads();
        float chg = __ldcg((const float*)&g_chg[bb][slot]);
        if (it >= 12 && chg < SINK_TOL) break;
    }
}

__global__ void sink_uvfin()
{
    int t = blockIdx.x * 256 + threadIdx.x;
    if (t < 4100) {
        g_u[t]  = logf(g_w[t]) - g_M[t];
        g_vv[t] = logf(g_ev[t]);
    }
}

__global__ void final_out(float* __restrict__ out)
{
    long t = (long)blockIdx.x * 256 + threadIdx.x;
    if (t >= 4202500L) return;
    int b = (int)(t / 1050625);
    int rem = (int)(t - (long)b * 1050625);
    int i = rem / 1025, j = rem - i * 1025;
    out[t] = g_coup[t] + g_u[b * 1025 + i] + g_vv[b * 1025 + j] - NORM_C;
}

// ======================= driver ======================================================
extern "C" void kernel_launch(void* const* d_in, const int* in_sizes, int n_in,
                              void* d_out, int out_size)
{
    (void)in_sizes; (void)n_in; (void)out_size;
    const float* Wq = (const float*)d_in[2];  const float* bq = (const float*)d_in[3];
    const float* Wk = (const float*)d_in[4];  const float* bk = (const float*)d_in[5];
    const float* Wv = (const float*)d_in[6];  const float* bv = (const float*)d_in[7];
    const float* Wm = (const float*)d_in[8];  const float* bm = (const float*)d_in[9];
    const float* W1 = (const float*)d_in[10]; const float* b1 = (const float*)d_in[11];
    const float* W2 = (const float*)d_in[12]; const float* b2 = (const float*)d_in[13];
    const float* Wf = (const float*)d_in[14]; const float* bf = (const float*)d_in[15];
    const float* bin = (const float*)d_in[16];

    cudaFuncSetAttribute(gemm_tc,    cudaFuncAttributeMaxDynamicSharedMemorySize, GEMM_SMEM);
    cudaFuncSetAttribute(gemm_h<0>,  cudaFuncAttributeMaxDynamicSharedMemorySize, GEMMH_SMEM);
    cudaFuncSetAttribute(gemm_h<1>,  cudaFuncAttributeMaxDynamicSharedMemorySize, GEMMH_SMEM);
    cudaFuncSetAttribute(flash_attn, cudaFuncAttributeMaxDynamicSharedMemorySize, FLASH_SMEM);

    float *pact, *pcoup, *pbpack, *pwmt, *pb1f;
    __half *pcath, *pzh, *pmfinh, *pwpackh, *pW1h, *pW2h, *pWfh;
    cudaGetSymbolAddress((void**)&pact,   g_act);
    cudaGetSymbolAddress((void**)&pcoup,  g_coup);
    cudaGetSymbolAddress((void**)&pbpack, g_bpack);
    cudaGetSymbolAddress((void**)&pwmt,   g_wmt);
    cudaGetSymbolAddress((void**)&pb1f,   g_b1f);
    cudaGetSymbolAddress((void**)&pcath,  g_cath);
    cudaGetSymbolAddress((void**)&pzh,    g_zh);
    cudaGetSymbolAddress((void**)&pmfinh, g_mfinh);
    cudaGetSymbolAddress((void**)&pwpackh,g_wpackh);
    cudaGetSymbolAddress((void**)&pW1h,   g_W1h);
    cudaGetSymbolAddress((void**)&pW2h,   g_W2h);
    cudaGetSymbolAddress((void**)&pWfh,   g_Wfh);

    pack_w<<<12288, 256>>>(Wq, Wk, Wv, bq, bk, bv, Wm, W1, W2, Wf);
    fold_b1<<<1536, 256>>>(W1, b1, bm);
    gemm_tc<<<dim3(4, 8, 12), 256, GEMM_SMEM>>>(
        W1 + 512, 1024, 1048576, pwmt, 512, 262144, pW1h + 512, 1024, 1048576, 512);

    float* cur = pact;
    float* nxt = pact + 4194304;
    init_inputs<<<4096, 256>>>((const float4*)d_in[0], (const float4*)d_in[1]);

    for (int i = 0; i < 12; i++) {
        const int cross = (i & 1);
        gemm_h<1><<<dim3(12, 64), 256, GEMMH_SMEM>>>(
            pcath, 1024, 0, pwpackh + (long)i * 786432, 512, 0,
            pbpack + i * 1536, nullptr, 0, 0, nullptr, nullptr, 0, 512, 1.f);
        flash_attn<<<dim3(8, 32, 2), 256, FLASH_SMEM>>>(cross);
        gemm_h<0><<<dim3(8, 64), 256, GEMMH_SMEM>>>(
            pcath, 1024, 0, pW1h + (long)i * 1048576, 1024, 0,
            pb1f + i * 1024, nullptr, 1024, 0, nullptr, pzh, 1024, 1024, 1.f);
        instnorm_relu<<<128, 256>>>();
        gemm_h<0><<<dim3(4, 64), 256, GEMMH_SMEM>>>(
            pzh, 1024, 0, pW2h + (long)i * 524288, 1024, 0,
            b2 + i * 512, nxt, 512, 0, cur, pcath, 1024, 1024, 1.f);
        float* tmp = cur; cur = nxt; nxt = tmp;
    }

    gemm_h<0><<<dim3(4, 64), 256, GEMMH_SMEM>>>(
        pcath, 1024, 0, pWfh, 512, 0, bf,
        nullptr, 0, 0, nullptr, pmfinh, 512, 512, 1.f);
    gemm_h<0><<<dim3(8, 8, 4), 256, GEMMH_SMEM>>>(
        pmfinh, 512, 524288, pmfinh + 2097152, 512, 524288, nullptr,
        pcoup, 1025, 1050625, nullptr, nullptr, 0, 512, 0.04419417382415922f);

    sink_prep<<<4100, 256>>>(bin);
    transP<<<dim3(33, 33, 4), dim3(32, 8)>>>();
    sink_persist<<<592, 256>>>();
    sink_uvfin<<<17, 256>>>();
    final_out<<<16417, 256>>>((float*)d_out);
}